// round 15
// baseline (speedup 1.0000x reference)
#include <cuda_runtime.h>
#include <cuda_fp16.h>
#include <math.h>
#include <stdint.h>

// Problem constants: B=4, K=64, L=128, D=768
#define NBK   256
#define LL    128
#define DD    768
#define NROWS 65536
#define NOUT  32768
#define EPSV  1e-8f

#define ASTRH 40    // scores fp16 smem row stride (80 B), ldmatrix conflict-free

// Scratch
__device__ float  g_norm[NROWS];
__device__ int    g_arg[NOUT];
__device__ float  g_y[NROWS];
__device__ __half g_w1h[DD * DD];            // w1^T fp16 [e][d]
__device__ __half g_xh[(size_t)NROWS * DD];  // normalized rows, fp16

__device__ __forceinline__ void ldsm_x4(uint32_t* r, uint32_t addr) {
    asm volatile("ldmatrix.sync.aligned.m8n8.x4.shared.b16 {%0,%1,%2,%3}, [%4];"
        : "=r"(r[0]), "=r"(r[1]), "=r"(r[2]), "=r"(r[3]) : "r"(addr));
}
__device__ __forceinline__ void mma_fp16(float* d, const uint32_t* a, const uint32_t* b) {
    asm volatile(
        "mma.sync.aligned.m16n8k16.row.col.f32.f16.f16.f32 "
        "{%0,%1,%2,%3}, {%4,%5,%6,%7}, {%8,%9}, {%0,%1,%2,%3};"
        : "+f"(d[0]), "+f"(d[1]), "+f"(d[2]), "+f"(d[3])
        : "r"(a[0]), "r"(a[1]), "r"(a[2]), "r"(a[3]), "r"(b[0]), "r"(b[1]));
}
__device__ __forceinline__ uint32_t smem_u32(const void* p) {
    uint32_t a;
    asm("{ .reg .u64 t; cvta.to.shared.u64 t, %1; cvt.u32.u64 %0, t; }" : "=r"(a) : "l"(p));
    return a;
}
__device__ __forceinline__ uint32_t pack2(float x, float y) {
    __half2 h = __floats2half2_rn(x, y);
    return *reinterpret_cast<uint32_t*>(&h);
}
__device__ __forceinline__ void split2(float x, float y, uint32_t& hi, uint32_t& lo) {
    __half hx = __float2half_rn(x), hy = __float2half_rn(y);
    float lx = x - __half2float(hx);
    float ly = y - __half2float(hy);
    __half2 hh = __halves2half2(hx, hy);
    hi = *reinterpret_cast<uint32_t*>(&hh);
    lo = pack2(lx, ly);
}
#define CP16(dst, src) \
    asm volatile("cp.async.cg.shared.global [%0], [%1], 16;" :: "r"(dst), "l"(src))
#define CP_COMMIT() asm volatile("cp.async.commit_group;" ::: "memory")
#define CP_WAIT(n)  asm volatile("cp.async.wait_group %0;" :: "n"(n) : "memory")

// ---------------------------------------------------------------------------
// Kernel A: fused norms + normalized-fp16 X (one warp per row)
// ---------------------------------------------------------------------------
__global__ void prep_x_kernel(const float* __restrict__ x) {
    int row  = blockIdx.x * 8 + (threadIdx.x >> 5);
    int lane = threadIdx.x & 31;
    const float4* p = reinterpret_cast<const float4*>(x) + (size_t)row * (DD / 4);
    float4 v[6];
    float s = 0.f;
    #pragma unroll
    for (int i = 0; i < 6; i++) {
        v[i] = p[lane + i * 32];
        s += v[i].x * v[i].x + v[i].y * v[i].y + v[i].z * v[i].z + v[i].w * v[i].w;
    }
    #pragma unroll
    for (int o = 16; o; o >>= 1) s += __shfl_xor_sync(0xffffffffu, s, o);
    float norm = sqrtf(s);
    if (lane == 0) g_norm[row] = norm;
    float inv = 1.0f / norm;
    uint2* dst = reinterpret_cast<uint2*>(g_xh + (size_t)row * DD);
    #pragma unroll
    for (int i = 0; i < 6; i++) {
        uint2 u;
        u.x = pack2(v[i].x * inv, v[i].y * inv);
        u.y = pack2(v[i].z * inv, v[i].w * inv);
        dst[lane + i * 32] = u;
    }
}

// ---------------------------------------------------------------------------
// Kernel B: w1 -> fp16, transposed to [e][d]
// ---------------------------------------------------------------------------
__global__ void prep_w1_kernel(const float* __restrict__ w1) {
    int e = blockIdx.x;
    for (int d = threadIdx.x; d < DD; d += 256)
        g_w1h[e * DD + d] = __float2half_rn(__ldg(w1 + (size_t)d * DD + e));
}

// ---------------------------------------------------------------------------
// MLP kernel: 128x128 tiles, 6 e-passes, KC=64; cp.async 3-STAGE pipeline,
// ONE __syncthreads per chunk iteration (buffer-reuse race is excluded by
// the sync chain: slot (c+2)%3 == slot (c-1)%3, whose compute finished
// before the sync at iteration c). 8 warps = 4(M) x 2(N), warp tile 32x64.
// ---------------------------------------------------------------------------
#define KC     64
#define ASTR2  72
#define ABYTES (128 * ASTR2 * 2)    // 18432 B per buffer
#define M_AS   0                    // 3 x 18432
#define M_BS   55296                // 3 x 18432
#define M_SRED 110592               // 256 f32
#define MLP_SMEM 111616

__global__ __launch_bounds__(256, 2) void mlp_kernel(const float* __restrict__ b1,
                                                     const float* __restrict__ w2,
                                                     const float* __restrict__ b2) {
    extern __shared__ char smem[];
    float* sred = reinterpret_cast<float*>(smem + M_SRED);
    uint32_t as_u32 = smem_u32(smem) + M_AS;
    uint32_t bs_u32 = smem_u32(smem) + M_BS;

    int rt = blockIdx.x;
    const __half* Xh = g_xh + (size_t)rt * LL * DD;

    int t    = threadIdx.x;
    int lane = t & 31;
    int wid  = t >> 5;
    int wm   = wid & 3;
    int wn   = wid >> 2;
    int lq   = lane >> 2;
    int lr   = lane & 3;

    int srow[4], sc16[4];
    #pragma unroll
    for (int it = 0; it < 4; it++) {
        int idx = t + it * 256;
        srow[it] = idx >> 3;
        sc16[it] = idx & 7;
    }

    uint32_t a_frag_base = as_u32 +
        (uint32_t)(((wm * 32 + (lane & 15)) * ASTR2 + (lane >> 4) * 8) * 2);
    uint32_t b_row_off = ((lane >> 4) * 8 + (lane & 7));
    uint32_t b_k_off   = ((lane >> 3) & 1) * 8;
    uint32_t b_frag_base = bs_u32 +
        (uint32_t)(((wn * 64 + b_row_off) * ASTR2 + b_k_off) * 2);

    float yacc[4] = {0.f, 0.f, 0.f, 0.f};

    for (int ec = 0; ec < 6; ec++) {
        float acc[2][8][4];
        #pragma unroll
        for (int mi = 0; mi < 2; mi++)
            #pragma unroll
            for (int ni = 0; ni < 8; ni++)
                #pragma unroll
                for (int c = 0; c < 4; c++) acc[mi][ni][c] = 0.f;

        auto issue = [&](int cidx, int buf) {
            int d0 = cidx * KC;
            #pragma unroll
            for (int it = 0; it < 4; it++) {
                uint32_t soff = (uint32_t)((srow[it] * ASTR2 + sc16[it] * 8) * 2)
                              + (uint32_t)buf * ABYTES;
                CP16(as_u32 + soff, Xh + (size_t)srow[it] * DD + d0 + sc16[it] * 8);
                CP16(bs_u32 + soff,
                     g_w1h + (size_t)(ec * 128 + srow[it]) * DD + d0 + sc16[it] * 8);
            }
        };

        issue(0, 0); CP_COMMIT();
        issue(1, 1); CP_COMMIT();

        for (int c = 0; c < 12; c++) {
            // need group c complete: outstanding allowed = 1 for c<11, 0 at c=11
            if (c < 11) { CP_WAIT(1); } else { CP_WAIT(0); }
            __syncthreads();
            // issue next-next chunk into slot (c+2)%3 == (c-1)%3 (safe: that
            // slot's compute finished before this sync on all warps)
            if (c < 10) { issue(c + 2, (c + 2) % 3); CP_COMMIT(); }

            int buf = c % 3;
            uint32_t abase = a_frag_base + buf * ABYTES;
            uint32_t bbase = b_frag_base + buf * ABYTES;
            #pragma unroll
            for (int kk = 0; kk < 4; kk++) {
                uint32_t a[2][4];
                #pragma unroll
                for (int mi = 0; mi < 2; mi++)
                    ldsm_x4(a[mi], abase + mi * (16 * ASTR2 * 2) + kk * 32);
                uint32_t b[4][4];
                #pragma unroll
                for (int nb = 0; nb < 4; nb++)
                    ldsm_x4(b[nb], bbase + nb * (16 * ASTR2 * 2) + kk * 32);
                #pragma unroll
                for (int mi = 0; mi < 2; mi++)
                    #pragma unroll
                    for (int nb = 0; nb < 4; nb++) {
                        mma_fp16(acc[mi][nb * 2 + 0], a[mi], &b[nb][0]);
                        mma_fp16(acc[mi][nb * 2 + 1], a[mi], &b[nb][2]);
                    }
            }
        }

        #pragma unroll
        for (int ni = 0; ni < 8; ni++) {
            int e0 = ec * 128 + wn * 64 + ni * 8 + lr * 2;
            float b1a = __ldg(b1 + e0),     b1b = __ldg(b1 + e0 + 1);
            float w2a = __ldg(w2 + e0),     w2b = __ldg(w2 + e0 + 1);
            #pragma unroll
            for (int mi = 0; mi < 2; mi++) {
                float h;
                h = acc[mi][ni][0] + b1a; if (h > 0.f) yacc[mi * 2 + 0] += h * w2a;
                h = acc[mi][ni][1] + b1b; if (h > 0.f) yacc[mi * 2 + 0] += h * w2b;
                h = acc[mi][ni][2] + b1a; if (h > 0.f) yacc[mi * 2 + 1] += h * w2a;
                h = acc[mi][ni][3] + b1b; if (h > 0.f) yacc[mi * 2 + 1] += h * w2b;
            }
        }
    }

    #pragma unroll
    for (int j = 0; j < 4; j++) {
        yacc[j] += __shfl_xor_sync(0xffffffffu, yacc[j], 1);
        yacc[j] += __shfl_xor_sync(0xffffffffu, yacc[j], 2);
    }
    if (lr == 0) {
        #pragma unroll
        for (int j = 0; j < 4; j++) {
            int row = wm * 32 + (j >> 1) * 16 + (j & 1) * 8 + lq;
            sred[row * 2 + wn] = yacc[j];
        }
    }
    __syncthreads();
    if (t < 128)
        g_y[rt * LL + t] = sred[t * 2] + sred[t * 2 + 1] + __ldg(b2);
}

// ---------------------------------------------------------------------------
// Scores kernel (R13 validated): 64 ctx rows x 128 ent cols per block
// (512 blocks), split-fp16 3-term; 8 warps = 2(M) x 4(N), warp tile 32x32.
// ---------------------------------------------------------------------------
#define S_AH   0
#define S_AL   5120
#define S_BH   10240
#define S_BL   20480
#define S_SNA  30720
#define S_SNB  30976
#define S_RV   31488
#define S_RI   32512
#define SC_SMEM 33536

__global__ __launch_bounds__(256, 2) void scores_kernel(const float* __restrict__ x) {
    extern __shared__ char smem[];
    uint32_t sb = smem_u32(smem);
    __half* Ah = reinterpret_cast<__half*>(smem + S_AH);
    __half* Al = reinterpret_cast<__half*>(smem + S_AL);
    __half* Bh = reinterpret_cast<__half*>(smem + S_BH);
    __half* Bl = reinterpret_cast<__half*>(smem + S_BL);
    float*  snA = reinterpret_cast<float*>(smem + S_SNA);
    float*  snB = reinterpret_cast<float*>(smem + S_SNB);
    float*  rv  = reinterpret_cast<float*>(smem + S_RV);
    int*    ri  = reinterpret_cast<int*>(smem + S_RI);

    int sid = blockIdx.x;
    int bk = sid >> 1;
    int lo = (sid & 1) * 64;
    const float* ctx = x + (size_t)(bk * 2) * LL * DD + (size_t)lo * DD;
    const float* ent = x + (size_t)(bk * 2 + 1) * LL * DD;

    int t    = threadIdx.x;
    int lane = t & 31;
    int wid  = t >> 5;
    int wm   = wid & 1;
    int wn   = wid >> 1;
    int lq   = lane >> 2;
    int lr   = lane & 3;

    if (t < 64)  snA[t] = g_norm[(bk * 2) * LL + lo + t];
    if (t < 128) snB[t] = g_norm[(bk * 2 + 1) * LL + t];

    int arow[2], ak4[2];
    #pragma unroll
    for (int it = 0; it < 2; it++) {
        int idx = t + it * 256;
        arow[it] = idx >> 3;  ak4[it] = idx & 7;
    }
    int brow[4], bk4[4];
    #pragma unroll
    for (int it = 0; it < 4; it++) {
        int idx = t + it * 256;
        brow[it] = idx >> 3;  bk4[it] = idx & 7;
    }

    uint32_t frag_a = (uint32_t)(((wm * 32 + (lane & 15)) * ASTRH + (lane >> 4) * 8) * 2);
    uint32_t b_row_off = ((lane >> 4) * 8 + (lane & 7));
    uint32_t b_k_off   = ((lane >> 3) & 1) * 8;
    uint32_t frag_b = (uint32_t)(((wn * 32 + b_row_off) * ASTRH + b_k_off) * 2);

    uint32_t ah_base = sb + S_AH + frag_a;
    uint32_t al_base = sb + S_AL + frag_a;
    uint32_t bh_base = sb + S_BH + frag_b;
    uint32_t bl_base = sb + S_BL + frag_b;

    float acc[2][4][4];
    #pragma unroll
    for (int mi = 0; mi < 2; mi++)
        #pragma unroll
        for (int ni = 0; ni < 4; ni++)
            #pragma unroll
            for (int c = 0; c < 4; c++) acc[mi][ni][c] = 0.f;

    float4 av[2], bw[4];
    #pragma unroll
    for (int it = 0; it < 2; it++)
        av[it] = *reinterpret_cast<const float4*>(ctx + (size_t)arow[it] * DD + ak4[it] * 4);
    #pragma unroll
    for (int it = 0; it < 4; it++)
        bw[it] = *reinterpret_cast<const float4*>(ent + (size_t)brow[it] * DD + bk4[it] * 4);

    for (int c = 0; c < 24; c++) {
        #pragma unroll
        for (int it = 0; it < 2; it++) {
            uint32_t off = arow[it] * ASTRH + ak4[it] * 4;
            uint2 h, l;
            split2(av[it].x, av[it].y, h.x, l.x);
            split2(av[it].z, av[it].w, h.y, l.y);
            *reinterpret_cast<uint2*>(&Ah[off]) = h;
            *reinterpret_cast<uint2*>(&Al[off]) = l;
        }
        #pragma unroll
        for (int it = 0; it < 4; it++) {
            uint32_t off = brow[it] * ASTRH + bk4[it] * 4;
            uint2 h, l;
            split2(bw[it].x, bw[it].y, h.x, l.x);
            split2(bw[it].z, bw[it].w, h.y, l.y);
            *reinterpret_cast<uint2*>(&Bh[off]) = h;
            *reinterpret_cast<uint2*>(&Bl[off]) = l;
        }
        __syncthreads();
        if (c < 23) {
            int d0 = (c + 1) * 32;
            #pragma unroll
            for (int it = 0; it < 2; it++)
                av[it] = *reinterpret_cast<const float4*>(ctx + (size_t)arow[it] * DD + d0 + ak4[it] * 4);
            #pragma unroll
            for (int it = 0; it < 4; it++)
                bw[it] = *reinterpret_cast<const float4*>(ent + (size_t)brow[it] * DD + d0 + bk4[it] * 4);
        }
        #pragma unroll
        for (int kk = 0; kk < 2; kk++) {
            uint32_t ah[2][4], al[2][4];
            #pragma unroll
            for (int mi = 0; mi < 2; mi++) {
                ldsm_x4(ah[mi], ah_base + mi * (16 * ASTRH * 2) + kk * 32);
                ldsm_x4(al[mi], al_base + mi * (16 * ASTRH * 2) + kk * 32);
            }
            #pragma unroll
            for (int nb = 0; nb < 2; nb++) {
                uint32_t bh[4];
                ldsm_x4(bh, bh_base + nb * (16 * ASTRH * 2) + kk * 32);
                #pragma unroll
                for (int mi = 0; mi < 2; mi++) {
                    mma_fp16(acc[mi][nb * 2 + 0], ah[mi], &bh[0]);
                    mma_fp16(acc[mi][nb * 2 + 1], ah[mi], &bh[2]);
                    mma_fp16(acc[mi][nb * 2 + 0], al[mi], &bh[0]);
                    mma_fp16(acc[mi][nb * 2 + 1], al[mi], &bh[2]);
                }
                uint32_t bl[4];
                ldsm_x4(bl, bl_base + nb * (16 * ASTRH * 2) + kk * 32);
                #pragma unroll
                for (int mi = 0; mi < 2; mi++) {
                    mma_fp16(acc[mi][nb * 2 + 0], ah[mi], &bl[0]);
                    mma_fp16(acc[mi][nb * 2 + 1], ah[mi], &bl[2]);
                }
            }
        }
        __syncthreads();
    }

    float bv[4];
    int   bi4[4];
    float nl[4];
    #pragma unroll
    for (int s = 0; s < 4; s++) {
        bv[s] = -3.4e38f; bi4[s] = 0;
        nl[s] = snA[wm * 32 + (s >> 1) * 16 + (s & 1) * 8 + lq];
    }
    #pragma unroll
    for (int ni = 0; ni < 4; ni++) {
        int col0 = wn * 32 + ni * 8 + lr * 2;
        float nm0 = snB[col0], nm1 = snB[col0 + 1];
        #pragma unroll
        for (int mi = 0; mi < 2; mi++) {
            float c0 = acc[mi][ni][0] / (nl[mi * 2] * nm0 + EPSV);
            if (c0 > bv[mi * 2]) { bv[mi * 2] = c0; bi4[mi * 2] = col0; }
            float c1 = acc[mi][ni][1] / (nl[mi * 2] * nm1 + EPSV);
            if (c1 > bv[mi * 2]) { bv[mi * 2] = c1; bi4[mi * 2] = col0 + 1; }
            float c2 = acc[mi][ni][2] / (nl[mi * 2 + 1] * nm0 + EPSV);
            if (c2 > bv[mi * 2 + 1]) { bv[mi * 2 + 1] = c2; bi4[mi * 2 + 1] = col0; }
            float c3 = acc[mi][ni][3] / (nl[mi * 2 + 1] * nm1 + EPSV);
            if (c3 > bv[mi * 2 + 1]) { bv[mi * 2 + 1] = c3; bi4[mi * 2 + 1] = col0 + 1; }
        }
    }
    #pragma unroll
    for (int s = 0; s < 4; s++) {
        #pragma unroll
        for (int o = 1; o <= 2; o <<= 1) {
            float ov = __shfl_xor_sync(0xffffffffu, bv[s], o);
            int   oi = __shfl_xor_sync(0xffffffffu, bi4[s], o);
            if (ov > bv[s] || (ov == bv[s] && oi < bi4[s])) { bv[s] = ov; bi4[s] = oi; }
        }
    }
    if (lr == 0) {
        #pragma unroll
        for (int s = 0; s < 4; s++) {
            int row = wm * 32 + (s >> 1) * 16 + (s & 1) * 8 + lq;
            rv[row * 4 + wn] = bv[s];
            ri[row * 4 + wn] = bi4[s];
        }
    }
    __syncthreads();
    if (t < 64) {
        float best = rv[t * 4]; int bi = ri[t * 4];
        #pragma unroll
        for (int j = 1; j < 4; j++) {
            float v = rv[t * 4 + j];
            int   i = ri[t * 4 + j];
            if (v > best || (v == best && i < bi)) { best = v; bi = i; }
        }
        g_arg[bk * LL + lo + t] = bi;
    }
}

// ---------------------------------------------------------------------------
// Kernel C: out = y_ctx + y_ent[argmax]
// ---------------------------------------------------------------------------
__global__ void finalize_kernel(float* __restrict__ out) {
    int i  = blockIdx.x * 256 + threadIdx.x;
    int bk = i >> 7;
    float yc = g_y[(bk * 2) * LL + (i & 127)];
    float ye = g_y[(bk * 2 + 1) * LL + g_arg[i]];
    out[i] = yc + ye;
}

extern "C" void kernel_launch(void* const* d_in, const int* in_sizes, int n_in,
                              void* d_out, int out_size) {
    const float* context = (const float*)d_in[0];
    const float* w1      = (const float*)d_in[1];
    const float* b1      = (const float*)d_in[2];
    const float* w2      = (const float*)d_in[3];
    const float* b2      = (const float*)d_in[4];
    float* out = (float*)d_out;

    cudaFuncSetAttribute(mlp_kernel,
                         cudaFuncAttributeMaxDynamicSharedMemorySize, MLP_SMEM);
    cudaFuncSetAttribute(scores_kernel,
                         cudaFuncAttributeMaxDynamicSharedMemorySize, SC_SMEM);

    prep_w1_kernel<<<DD, 256>>>(w1);
    prep_x_kernel<<<NROWS / 8, 256>>>(context);
    scores_kernel<<<512, 256, SC_SMEM>>>(context);
    mlp_kernel<<<NROWS / 128, 256, MLP_SMEM>>>(b1, w2, b2);
    finalize_kernel<<<NOUT / 256, 256>>>(out);
}

// round 16
// speedup vs baseline: 1.4579x; 1.4579x over previous
#include <cuda_runtime.h>
#include <cuda_fp16.h>
#include <math.h>
#include <stdint.h>

// Problem constants: B=4, K=64, L=128, D=768
#define NBK   256
#define LL    128
#define DD    768
#define NROWS 65536
#define NOUT  32768
#define EPSV  1e-8f

#define ASTRH 40    // scores fp16 smem row stride (80 B), ldmatrix conflict-free

// Scratch
__device__ float  g_norm[NROWS];
__device__ int    g_arg[NOUT];
__device__ float  g_y[NROWS];
__device__ __half g_w1h[DD * DD];            // w1^T fp16 [e][d]
__device__ __half g_xh[(size_t)NROWS * DD];  // normalized rows, fp16

__device__ __forceinline__ void ldsm_x4(uint32_t* r, uint32_t addr) {
    asm volatile("ldmatrix.sync.aligned.m8n8.x4.shared.b16 {%0,%1,%2,%3}, [%4];"
        : "=r"(r[0]), "=r"(r[1]), "=r"(r[2]), "=r"(r[3]) : "r"(addr));
}
__device__ __forceinline__ void mma_fp16(float* d, const uint32_t* a, const uint32_t* b) {
    asm volatile(
        "mma.sync.aligned.m16n8k16.row.col.f32.f16.f16.f32 "
        "{%0,%1,%2,%3}, {%4,%5,%6,%7}, {%8,%9}, {%0,%1,%2,%3};"
        : "+f"(d[0]), "+f"(d[1]), "+f"(d[2]), "+f"(d[3])
        : "r"(a[0]), "r"(a[1]), "r"(a[2]), "r"(a[3]), "r"(b[0]), "r"(b[1]));
}
__device__ __forceinline__ uint32_t smem_u32(const void* p) {
    uint32_t a;
    asm("{ .reg .u64 t; cvta.to.shared.u64 t, %1; cvt.u32.u64 %0, t; }" : "=r"(a) : "l"(p));
    return a;
}
__device__ __forceinline__ uint32_t pack2(float x, float y) {
    __half2 h = __floats2half2_rn(x, y);
    return *reinterpret_cast<uint32_t*>(&h);
}
__device__ __forceinline__ void split2(float x, float y, uint32_t& hi, uint32_t& lo) {
    __half hx = __float2half_rn(x), hy = __float2half_rn(y);
    float lx = x - __half2float(hx);
    float ly = y - __half2float(hy);
    __half2 hh = __halves2half2(hx, hy);
    hi = *reinterpret_cast<uint32_t*>(&hh);
    lo = pack2(lx, ly);
}
#define CP16(dst, src) \
    asm volatile("cp.async.cg.shared.global [%0], [%1], 16;" :: "r"(dst), "l"(src))
#define CP_COMMIT() asm volatile("cp.async.commit_group;" ::: "memory")
#define CP_WAIT(n)  asm volatile("cp.async.wait_group %0;" :: "n"(n) : "memory")

// ---------------------------------------------------------------------------
// Kernel A: fused norms + normalized-fp16 X (one warp per row)
// ---------------------------------------------------------------------------
__global__ void prep_x_kernel(const float* __restrict__ x) {
    int row  = blockIdx.x * 8 + (threadIdx.x >> 5);
    int lane = threadIdx.x & 31;
    const float4* p = reinterpret_cast<const float4*>(x) + (size_t)row * (DD / 4);
    float4 v[6];
    float s = 0.f;
    #pragma unroll
    for (int i = 0; i < 6; i++) {
        v[i] = p[lane + i * 32];
        s += v[i].x * v[i].x + v[i].y * v[i].y + v[i].z * v[i].z + v[i].w * v[i].w;
    }
    #pragma unroll
    for (int o = 16; o; o >>= 1) s += __shfl_xor_sync(0xffffffffu, s, o);
    float norm = sqrtf(s);
    if (lane == 0) g_norm[row] = norm;
    float inv = 1.0f / norm;
    uint2* dst = reinterpret_cast<uint2*>(g_xh + (size_t)row * DD);
    #pragma unroll
    for (int i = 0; i < 6; i++) {
        uint2 u;
        u.x = pack2(v[i].x * inv, v[i].y * inv);
        u.y = pack2(v[i].z * inv, v[i].w * inv);
        dst[lane + i * 32] = u;
    }
}

// ---------------------------------------------------------------------------
// Kernel B: w1 -> fp16, transposed to [e][d]
// ---------------------------------------------------------------------------
__global__ void prep_w1_kernel(const float* __restrict__ w1) {
    int e = blockIdx.x;
    for (int d = threadIdx.x; d < DD; d += 256)
        g_w1h[e * DD + d] = __float2half_rn(__ldg(w1 + (size_t)d * DD + e));
}

// ---------------------------------------------------------------------------
// MLP kernel (R13, validated 250.8us @ tensor 50.8%): 128x128 tiles,
// 6 e-passes, KC=64, cp.async 2-stage double-buffered, stride-72 rows.
// 8 warps = 4(M) x 2(N), warp tile 32x64.
// ---------------------------------------------------------------------------
#define KC     64
#define ASTR2  72
#define ABYTES (128 * ASTR2 * 2)    // 18432 B per buffer
#define M_AS   0                    // 2 x 18432
#define M_BS   36864                // 2 x 18432
#define M_SRED 73728                // 256 f32
#define MLP_SMEM 74752

__global__ __launch_bounds__(256, 2) void mlp_kernel(const float* __restrict__ b1,
                                                     const float* __restrict__ w2,
                                                     const float* __restrict__ b2) {
    extern __shared__ char smem[];
    float* sred = reinterpret_cast<float*>(smem + M_SRED);
    uint32_t as_u32 = smem_u32(smem) + M_AS;
    uint32_t bs_u32 = smem_u32(smem) + M_BS;

    int rt = blockIdx.x;
    const __half* Xh = g_xh + (size_t)rt * LL * DD;

    int t    = threadIdx.x;
    int lane = t & 31;
    int wid  = t >> 5;
    int wm   = wid & 3;
    int wn   = wid >> 2;
    int lq   = lane >> 2;
    int lr   = lane & 3;

    int srow[4], sc16[4];
    #pragma unroll
    for (int it = 0; it < 4; it++) {
        int idx = t + it * 256;
        srow[it] = idx >> 3;
        sc16[it] = idx & 7;
    }

    uint32_t a_frag_base = as_u32 +
        (uint32_t)(((wm * 32 + (lane & 15)) * ASTR2 + (lane >> 4) * 8) * 2);
    uint32_t b_row_off = ((lane >> 4) * 8 + (lane & 7));
    uint32_t b_k_off   = ((lane >> 3) & 1) * 8;
    uint32_t b_frag_base = bs_u32 +
        (uint32_t)(((wn * 64 + b_row_off) * ASTR2 + b_k_off) * 2);

    float yacc[4] = {0.f, 0.f, 0.f, 0.f};

    for (int ec = 0; ec < 6; ec++) {
        float acc[2][8][4];
        #pragma unroll
        for (int mi = 0; mi < 2; mi++)
            #pragma unroll
            for (int ni = 0; ni < 8; ni++)
                #pragma unroll
                for (int c = 0; c < 4; c++) acc[mi][ni][c] = 0.f;

        auto issue = [&](int cidx, int buf) {
            int d0 = cidx * KC;
            #pragma unroll
            for (int it = 0; it < 4; it++) {
                uint32_t soff = (uint32_t)((srow[it] * ASTR2 + sc16[it] * 8) * 2)
                              + (uint32_t)buf * ABYTES;
                CP16(as_u32 + soff, Xh + (size_t)srow[it] * DD + d0 + sc16[it] * 8);
                CP16(bs_u32 + soff,
                     g_w1h + (size_t)(ec * 128 + srow[it]) * DD + d0 + sc16[it] * 8);
            }
        };

        issue(0, 0);
        CP_COMMIT();

        for (int c = 0; c < 12; c++) {
            int buf = c & 1;
            if (c < 11) {
                issue(c + 1, buf ^ 1);
                CP_COMMIT();
                CP_WAIT(1);
            } else {
                CP_WAIT(0);
            }
            __syncthreads();

            uint32_t abase = a_frag_base + buf * ABYTES;
            uint32_t bbase = b_frag_base + buf * ABYTES;
            #pragma unroll
            for (int kk = 0; kk < 4; kk++) {
                uint32_t a[2][4];
                #pragma unroll
                for (int mi = 0; mi < 2; mi++)
                    ldsm_x4(a[mi], abase + mi * (16 * ASTR2 * 2) + kk * 32);
                uint32_t b[4][4];
                #pragma unroll
                for (int nb = 0; nb < 4; nb++)
                    ldsm_x4(b[nb], bbase + nb * (16 * ASTR2 * 2) + kk * 32);
                #pragma unroll
                for (int mi = 0; mi < 2; mi++)
                    #pragma unroll
                    for (int nb = 0; nb < 4; nb++) {
                        mma_fp16(acc[mi][nb * 2 + 0], a[mi], &b[nb][0]);
                        mma_fp16(acc[mi][nb * 2 + 1], a[mi], &b[nb][2]);
                    }
            }
            __syncthreads();
        }

        #pragma unroll
        for (int ni = 0; ni < 8; ni++) {
            int e0 = ec * 128 + wn * 64 + ni * 8 + lr * 2;
            float b1a = __ldg(b1 + e0),     b1b = __ldg(b1 + e0 + 1);
            float w2a = __ldg(w2 + e0),     w2b = __ldg(w2 + e0 + 1);
            #pragma unroll
            for (int mi = 0; mi < 2; mi++) {
                float h;
                h = acc[mi][ni][0] + b1a; if (h > 0.f) yacc[mi * 2 + 0] += h * w2a;
                h = acc[mi][ni][1] + b1b; if (h > 0.f) yacc[mi * 2 + 0] += h * w2b;
                h = acc[mi][ni][2] + b1a; if (h > 0.f) yacc[mi * 2 + 1] += h * w2a;
                h = acc[mi][ni][3] + b1b; if (h > 0.f) yacc[mi * 2 + 1] += h * w2b;
            }
        }
    }

    #pragma unroll
    for (int j = 0; j < 4; j++) {
        yacc[j] += __shfl_xor_sync(0xffffffffu, yacc[j], 1);
        yacc[j] += __shfl_xor_sync(0xffffffffu, yacc[j], 2);
    }
    if (lr == 0) {
        #pragma unroll
        for (int j = 0; j < 4; j++) {
            int row = wm * 32 + (j >> 1) * 16 + (j & 1) * 8 + lq;
            sred[row * 2 + wn] = yacc[j];
        }
    }
    __syncthreads();
    if (t < 128)
        g_y[rt * LL + t] = sred[t * 2] + sred[t * 2 + 1] + __ldg(b2);
}

// ---------------------------------------------------------------------------
// Scores kernel (R13 validated): 64 ctx rows x 128 ent cols per block
// (512 blocks), split-fp16 3-term; 8 warps = 2(M) x 4(N), warp tile 32x32.
// ---------------------------------------------------------------------------
#define S_AH   0
#define S_AL   5120
#define S_BH   10240
#define S_BL   20480
#define S_SNA  30720
#define S_SNB  30976
#define S_RV   31488
#define S_RI   32512
#define SC_SMEM 33536

__global__ __launch_bounds__(256, 2) void scores_kernel(const float* __restrict__ x) {
    extern __shared__ char smem[];
    uint32_t sb = smem_u32(smem);
    __half* Ah = reinterpret_cast<__half*>(smem + S_AH);
    __half* Al = reinterpret_cast<__half*>(smem + S_AL);
    __half* Bh = reinterpret_cast<__half*>(smem + S_BH);
    __half* Bl = reinterpret_cast<__half*>(smem + S_BL);
    float*  snA = reinterpret_cast<float*>(smem + S_SNA);
    float*  snB = reinterpret_cast<float*>(smem + S_SNB);
    float*  rv  = reinterpret_cast<float*>(smem + S_RV);
    int*    ri  = reinterpret_cast<int*>(smem + S_RI);

    int sid = blockIdx.x;
    int bk = sid >> 1;
    int lo = (sid & 1) * 64;
    const float* ctx = x + (size_t)(bk * 2) * LL * DD + (size_t)lo * DD;
    const float* ent = x + (size_t)(bk * 2 + 1) * LL * DD;

    int t    = threadIdx.x;
    int lane = t & 31;
    int wid  = t >> 5;
    int wm   = wid & 1;
    int wn   = wid >> 1;
    int lq   = lane >> 2;
    int lr   = lane & 3;

    if (t < 64)  snA[t] = g_norm[(bk * 2) * LL + lo + t];
    if (t < 128) snB[t] = g_norm[(bk * 2 + 1) * LL + t];

    int arow[2], ak4[2];
    #pragma unroll
    for (int it = 0; it < 2; it++) {
        int idx = t + it * 256;
        arow[it] = idx >> 3;  ak4[it] = idx & 7;
    }
    int brow[4], bk4[4];
    #pragma unroll
    for (int it = 0; it < 4; it++) {
        int idx = t + it * 256;
        brow[it] = idx >> 3;  bk4[it] = idx & 7;
    }

    uint32_t frag_a = (uint32_t)(((wm * 32 + (lane & 15)) * ASTRH + (lane >> 4) * 8) * 2);
    uint32_t b_row_off = ((lane >> 4) * 8 + (lane & 7));
    uint32_t b_k_off   = ((lane >> 3) & 1) * 8;
    uint32_t frag_b = (uint32_t)(((wn * 32 + b_row_off) * ASTRH + b_k_off) * 2);

    uint32_t ah_base = sb + S_AH + frag_a;
    uint32_t al_base = sb + S_AL + frag_a;
    uint32_t bh_base = sb + S_BH + frag_b;
    uint32_t bl_base = sb + S_BL + frag_b;

    float acc[2][4][4];
    #pragma unroll
    for (int mi = 0; mi < 2; mi++)
        #pragma unroll
        for (int ni = 0; ni < 4; ni++)
            #pragma unroll
            for (int c = 0; c < 4; c++) acc[mi][ni][c] = 0.f;

    float4 av[2], bw[4];
    #pragma unroll
    for (int it = 0; it < 2; it++)
        av[it] = *reinterpret_cast<const float4*>(ctx + (size_t)arow[it] * DD + ak4[it] * 4);
    #pragma unroll
    for (int it = 0; it < 4; it++)
        bw[it] = *reinterpret_cast<const float4*>(ent + (size_t)brow[it] * DD + bk4[it] * 4);

    for (int c = 0; c < 24; c++) {
        #pragma unroll
        for (int it = 0; it < 2; it++) {
            uint32_t off = arow[it] * ASTRH + ak4[it] * 4;
            uint2 h, l;
            split2(av[it].x, av[it].y, h.x, l.x);
            split2(av[it].z, av[it].w, h.y, l.y);
            *reinterpret_cast<uint2*>(&Ah[off]) = h;
            *reinterpret_cast<uint2*>(&Al[off]) = l;
        }
        #pragma unroll
        for (int it = 0; it < 4; it++) {
            uint32_t off = brow[it] * ASTRH + bk4[it] * 4;
            uint2 h, l;
            split2(bw[it].x, bw[it].y, h.x, l.x);
            split2(bw[it].z, bw[it].w, h.y, l.y);
            *reinterpret_cast<uint2*>(&Bh[off]) = h;
            *reinterpret_cast<uint2*>(&Bl[off]) = l;
        }
        __syncthreads();
        if (c < 23) {
            int d0 = (c + 1) * 32;
            #pragma unroll
            for (int it = 0; it < 2; it++)
                av[it] = *reinterpret_cast<const float4*>(ctx + (size_t)arow[it] * DD + d0 + ak4[it] * 4);
            #pragma unroll
            for (int it = 0; it < 4; it++)
                bw[it] = *reinterpret_cast<const float4*>(ent + (size_t)brow[it] * DD + d0 + bk4[it] * 4);
        }
        #pragma unroll
        for (int kk = 0; kk < 2; kk++) {
            uint32_t ah[2][4], al[2][4];
            #pragma unroll
            for (int mi = 0; mi < 2; mi++) {
                ldsm_x4(ah[mi], ah_base + mi * (16 * ASTRH * 2) + kk * 32);
                ldsm_x4(al[mi], al_base + mi * (16 * ASTRH * 2) + kk * 32);
            }
            #pragma unroll
            for (int nb = 0; nb < 2; nb++) {
                uint32_t bh[4];
                ldsm_x4(bh, bh_base + nb * (16 * ASTRH * 2) + kk * 32);
                #pragma unroll
                for (int mi = 0; mi < 2; mi++) {
                    mma_fp16(acc[mi][nb * 2 + 0], ah[mi], &bh[0]);
                    mma_fp16(acc[mi][nb * 2 + 1], ah[mi], &bh[2]);
                    mma_fp16(acc[mi][nb * 2 + 0], al[mi], &bh[0]);
                    mma_fp16(acc[mi][nb * 2 + 1], al[mi], &bh[2]);
                }
                uint32_t bl[4];
                ldsm_x4(bl, bl_base + nb * (16 * ASTRH * 2) + kk * 32);
                #pragma unroll
                for (int mi = 0; mi < 2; mi++) {
                    mma_fp16(acc[mi][nb * 2 + 0], ah[mi], &bl[0]);
                    mma_fp16(acc[mi][nb * 2 + 1], ah[mi], &bl[2]);
                }
            }
        }
        __syncthreads();
    }

    float bv[4];
    int   bi4[4];
    float nl[4];
    #pragma unroll
    for (int s = 0; s < 4; s++) {
        bv[s] = -3.4e38f; bi4[s] = 0;
        nl[s] = snA[wm * 32 + (s >> 1) * 16 + (s & 1) * 8 + lq];
    }
    #pragma unroll
    for (int ni = 0; ni < 4; ni++) {
        int col0 = wn * 32 + ni * 8 + lr * 2;
        float nm0 = snB[col0], nm1 = snB[col0 + 1];
        #pragma unroll
        for (int mi = 0; mi < 2; mi++) {
            float c0 = acc[mi][ni][0] / (nl[mi * 2] * nm0 + EPSV);
            if (c0 > bv[mi * 2]) { bv[mi * 2] = c0; bi4[mi * 2] = col0; }
            float c1 = acc[mi][ni][1] / (nl[mi * 2] * nm1 + EPSV);
            if (c1 > bv[mi * 2]) { bv[mi * 2] = c1; bi4[mi * 2] = col0 + 1; }
            float c2 = acc[mi][ni][2] / (nl[mi * 2 + 1] * nm0 + EPSV);
            if (c2 > bv[mi * 2 + 1]) { bv[mi * 2 + 1] = c2; bi4[mi * 2 + 1] = col0; }
            float c3 = acc[mi][ni][3] / (nl[mi * 2 + 1] * nm1 + EPSV);
            if (c3 > bv[mi * 2 + 1]) { bv[mi * 2 + 1] = c3; bi4[mi * 2 + 1] = col0 + 1; }
        }
    }
    #pragma unroll
    for (int s = 0; s < 4; s++) {
        #pragma unroll
        for (int o = 1; o <= 2; o <<= 1) {
            float ov = __shfl_xor_sync(0xffffffffu, bv[s], o);
            int   oi = __shfl_xor_sync(0xffffffffu, bi4[s], o);
            if (ov > bv[s] || (ov == bv[s] && oi < bi4[s])) { bv[s] = ov; bi4[s] = oi; }
        }
    }
    if (lr == 0) {
        #pragma unroll
        for (int s = 0; s < 4; s++) {
            int row = wm * 32 + (s >> 1) * 16 + (s & 1) * 8 + lq;
            rv[row * 4 + wn] = bv[s];
            ri[row * 4 + wn] = bi4[s];
        }
    }
    __syncthreads();
    if (t < 64) {
        float best = rv[t * 4]; int bi = ri[t * 4];
        #pragma unroll
        for (int j = 1; j < 4; j++) {
            float v = rv[t * 4 + j];
            int   i = ri[t * 4 + j];
            if (v > best || (v == best && i < bi)) { best = v; bi = i; }
        }
        g_arg[bk * LL + lo + t] = bi;
    }
}

// ---------------------------------------------------------------------------
// Kernel C: out = y_ctx + y_ent[argmax]
// ---------------------------------------------------------------------------
__global__ void finalize_kernel(float* __restrict__ out) {
    int i  = blockIdx.x * 256 + threadIdx.x;
    int bk = i >> 7;
    float yc = g_y[(bk * 2) * LL + (i & 127)];
    float ye = g_y[(bk * 2 + 1) * LL + g_arg[i]];
    out[i] = yc + ye;
}

extern "C" void kernel_launch(void* const* d_in, const int* in_sizes, int n_in,
                              void* d_out, int out_size) {
    const float* context = (const float*)d_in[0];
    const float* w1      = (const float*)d_in[1];
    const float* b1      = (const float*)d_in[2];
    const float* w2      = (const float*)d_in[3];
    const float* b2      = (const float*)d_in[4];
    float* out = (float*)d_out;

    cudaFuncSetAttribute(mlp_kernel,
                         cudaFuncAttributeMaxDynamicSharedMemorySize, MLP_SMEM);
    cudaFuncSetAttribute(scores_kernel,
                         cudaFuncAttributeMaxDynamicSharedMemorySize, SC_SMEM);

    prep_w1_kernel<<<DD, 256>>>(w1);
    prep_x_kernel<<<NROWS / 8, 256>>>(context);
    scores_kernel<<<512, 256, SC_SMEM>>>(context);
    mlp_kernel<<<NROWS / 128, 256, MLP_SMEM>>>(b1, w2, b2);
    finalize_kernel<<<NOUT / 256, 256>>>(out);
}

// round 17
// speedup vs baseline: 1.4815x; 1.0161x over previous
#include <cuda_runtime.h>
#include <cuda_fp16.h>
#include <math.h>
#include <stdint.h>

// Problem constants: B=4, K=64, L=128, D=768
#define NBK   256
#define LL    128
#define DD    768
#define NROWS 65536
#define NOUT  32768
#define EPSV  1e-8f

#define ASTRH 40    // scores fp16 smem row stride (80 B), ldmatrix conflict-free

// Scratch
__device__ float  g_norm[NROWS];
__device__ int    g_arg[NOUT];
__device__ float  g_y[NROWS];
__device__ __half g_w1h[DD * DD];            // w1^T fp16 [e][d]
__device__ __half g_xh[(size_t)NROWS * DD];  // normalized rows, fp16

__device__ __forceinline__ void ldsm_x4(uint32_t* r, uint32_t addr) {
    asm volatile("ldmatrix.sync.aligned.m8n8.x4.shared.b16 {%0,%1,%2,%3}, [%4];"
        : "=r"(r[0]), "=r"(r[1]), "=r"(r[2]), "=r"(r[3]) : "r"(addr));
}
__device__ __forceinline__ void mma_fp16(float* d, const uint32_t* a, const uint32_t* b) {
    asm volatile(
        "mma.sync.aligned.m16n8k16.row.col.f32.f16.f16.f32 "
        "{%0,%1,%2,%3}, {%4,%5,%6,%7}, {%8,%9}, {%0,%1,%2,%3};"
        : "+f"(d[0]), "+f"(d[1]), "+f"(d[2]), "+f"(d[3])
        : "r"(a[0]), "r"(a[1]), "r"(a[2]), "r"(a[3]), "r"(b[0]), "r"(b[1]));
}
__device__ __forceinline__ uint32_t smem_u32(const void* p) {
    uint32_t a;
    asm("{ .reg .u64 t; cvta.to.shared.u64 t, %1; cvt.u32.u64 %0, t; }" : "=r"(a) : "l"(p));
    return a;
}
__device__ __forceinline__ uint32_t pack2(float x, float y) {
    __half2 h = __floats2half2_rn(x, y);
    return *reinterpret_cast<uint32_t*>(&h);
}
__device__ __forceinline__ void split2(float x, float y, uint32_t& hi, uint32_t& lo) {
    __half hx = __float2half_rn(x), hy = __float2half_rn(y);
    float lx = x - __half2float(hx);
    float ly = y - __half2float(hy);
    __half2 hh = __halves2half2(hx, hy);
    hi = *reinterpret_cast<uint32_t*>(&hh);
    lo = pack2(lx, ly);
}
#define CP16(dst, src) \
    asm volatile("cp.async.cg.shared.global [%0], [%1], 16;" :: "r"(dst), "l"(src))
#define CP_COMMIT() asm volatile("cp.async.commit_group;" ::: "memory")
#define CP_WAIT(n)  asm volatile("cp.async.wait_group %0;" :: "n"(n) : "memory")

// ---------------------------------------------------------------------------
// Kernel A: fused norms + normalized-fp16 X (one warp per row)
// ---------------------------------------------------------------------------
__global__ void prep_x_kernel(const float* __restrict__ x) {
    int row  = blockIdx.x * 8 + (threadIdx.x >> 5);
    int lane = threadIdx.x & 31;
    const float4* p = reinterpret_cast<const float4*>(x) + (size_t)row * (DD / 4);
    float4 v[6];
    float s = 0.f;
    #pragma unroll
    for (int i = 0; i < 6; i++) {
        v[i] = p[lane + i * 32];
        s += v[i].x * v[i].x + v[i].y * v[i].y + v[i].z * v[i].z + v[i].w * v[i].w;
    }
    #pragma unroll
    for (int o = 16; o; o >>= 1) s += __shfl_xor_sync(0xffffffffu, s, o);
    float norm = sqrtf(s);
    if (lane == 0) g_norm[row] = norm;
    float inv = 1.0f / norm;
    uint2* dst = reinterpret_cast<uint2*>(g_xh + (size_t)row * DD);
    #pragma unroll
    for (int i = 0; i < 6; i++) {
        uint2 u;
        u.x = pack2(v[i].x * inv, v[i].y * inv);
        u.y = pack2(v[i].z * inv, v[i].w * inv);
        dst[lane + i * 32] = u;
    }
}

// ---------------------------------------------------------------------------
// Kernel B: w1 -> fp16, transposed to [e][d]
// ---------------------------------------------------------------------------
__global__ void prep_w1_kernel(const float* __restrict__ w1) {
    int e = blockIdx.x;
    for (int d = threadIdx.x; d < DD; d += 256)
        g_w1h[e * DD + d] = __float2half_rn(__ldg(w1 + (size_t)d * DD + e));
}

// ---------------------------------------------------------------------------
// MLP body (R13, validated): 128x128 tiles, 6 e-passes, KC=64, cp.async
// 2-stage double-buffered, stride-72 rows. 8 warps = 4(M) x 2(N).
// ---------------------------------------------------------------------------
#define KC     64
#define ASTR2  72
#define ABYTES (128 * ASTR2 * 2)    // 18432 B per buffer
#define M_AS   0                    // 2 x 18432
#define M_BS   36864                // 2 x 18432
#define M_SRED 73728                // 256 f32
#define MEGA_SMEM 74752

__device__ __forceinline__ void mlp_body(char* smem, int rt,
                                         const float* __restrict__ b1,
                                         const float* __restrict__ w2,
                                         const float* __restrict__ b2) {
    float* sred = reinterpret_cast<float*>(smem + M_SRED);
    uint32_t as_u32 = smem_u32(smem) + M_AS;
    uint32_t bs_u32 = smem_u32(smem) + M_BS;

    const __half* Xh = g_xh + (size_t)rt * LL * DD;

    int t    = threadIdx.x;
    int lane = t & 31;
    int wid  = t >> 5;
    int wm   = wid & 3;
    int wn   = wid >> 2;
    int lq   = lane >> 2;
    int lr   = lane & 3;

    int srow[4], sc16[4];
    #pragma unroll
    for (int it = 0; it < 4; it++) {
        int idx = t + it * 256;
        srow[it] = idx >> 3;
        sc16[it] = idx & 7;
    }

    uint32_t a_frag_base = as_u32 +
        (uint32_t)(((wm * 32 + (lane & 15)) * ASTR2 + (lane >> 4) * 8) * 2);
    uint32_t b_row_off = ((lane >> 4) * 8 + (lane & 7));
    uint32_t b_k_off   = ((lane >> 3) & 1) * 8;
    uint32_t b_frag_base = bs_u32 +
        (uint32_t)(((wn * 64 + b_row_off) * ASTR2 + b_k_off) * 2);

    float yacc[4] = {0.f, 0.f, 0.f, 0.f};

    for (int ec = 0; ec < 6; ec++) {
        float acc[2][8][4];
        #pragma unroll
        for (int mi = 0; mi < 2; mi++)
            #pragma unroll
            for (int ni = 0; ni < 8; ni++)
                #pragma unroll
                for (int c = 0; c < 4; c++) acc[mi][ni][c] = 0.f;

        auto issue = [&](int cidx, int buf) {
            int d0 = cidx * KC;
            #pragma unroll
            for (int it = 0; it < 4; it++) {
                uint32_t soff = (uint32_t)((srow[it] * ASTR2 + sc16[it] * 8) * 2)
                              + (uint32_t)buf * ABYTES;
                CP16(as_u32 + soff, Xh + (size_t)srow[it] * DD + d0 + sc16[it] * 8);
                CP16(bs_u32 + soff,
                     g_w1h + (size_t)(ec * 128 + srow[it]) * DD + d0 + sc16[it] * 8);
            }
        };

        issue(0, 0);
        CP_COMMIT();

        for (int c = 0; c < 12; c++) {
            int buf = c & 1;
            if (c < 11) {
                issue(c + 1, buf ^ 1);
                CP_COMMIT();
                CP_WAIT(1);
            } else {
                CP_WAIT(0);
            }
            __syncthreads();

            uint32_t abase = a_frag_base + buf * ABYTES;
            uint32_t bbase = b_frag_base + buf * ABYTES;
            #pragma unroll
            for (int kk = 0; kk < 4; kk++) {
                uint32_t a[2][4];
                #pragma unroll
                for (int mi = 0; mi < 2; mi++)
                    ldsm_x4(a[mi], abase + mi * (16 * ASTR2 * 2) + kk * 32);
                uint32_t b[4][4];
                #pragma unroll
                for (int nb = 0; nb < 4; nb++)
                    ldsm_x4(b[nb], bbase + nb * (16 * ASTR2 * 2) + kk * 32);
                #pragma unroll
                for (int mi = 0; mi < 2; mi++)
                    #pragma unroll
                    for (int nb = 0; nb < 4; nb++) {
                        mma_fp16(acc[mi][nb * 2 + 0], a[mi], &b[nb][0]);
                        mma_fp16(acc[mi][nb * 2 + 1], a[mi], &b[nb][2]);
                    }
            }
            __syncthreads();
        }

        #pragma unroll
        for (int ni = 0; ni < 8; ni++) {
            int e0 = ec * 128 + wn * 64 + ni * 8 + lr * 2;
            float b1a = __ldg(b1 + e0),     b1b = __ldg(b1 + e0 + 1);
            float w2a = __ldg(w2 + e0),     w2b = __ldg(w2 + e0 + 1);
            #pragma unroll
            for (int mi = 0; mi < 2; mi++) {
                float h;
                h = acc[mi][ni][0] + b1a; if (h > 0.f) yacc[mi * 2 + 0] += h * w2a;
                h = acc[mi][ni][1] + b1b; if (h > 0.f) yacc[mi * 2 + 0] += h * w2b;
                h = acc[mi][ni][2] + b1a; if (h > 0.f) yacc[mi * 2 + 1] += h * w2a;
                h = acc[mi][ni][3] + b1b; if (h > 0.f) yacc[mi * 2 + 1] += h * w2b;
            }
        }
    }

    #pragma unroll
    for (int j = 0; j < 4; j++) {
        yacc[j] += __shfl_xor_sync(0xffffffffu, yacc[j], 1);
        yacc[j] += __shfl_xor_sync(0xffffffffu, yacc[j], 2);
    }
    if (lr == 0) {
        #pragma unroll
        for (int j = 0; j < 4; j++) {
            int row = wm * 32 + (j >> 1) * 16 + (j & 1) * 8 + lq;
            sred[row * 2 + wn] = yacc[j];
        }
    }
    __syncthreads();
    if (t < 128)
        g_y[rt * LL + t] = sred[t * 2] + sred[t * 2 + 1] + __ldg(b2);
}

// ---------------------------------------------------------------------------
// Scores body (R13, validated): 64 ctx rows x 128 ent cols per tile,
// split-fp16 3-term; 8 warps = 2(M) x 4(N), warp tile 32x32.
// ---------------------------------------------------------------------------
#define S_AH   0
#define S_AL   5120
#define S_BH   10240
#define S_BL   20480
#define S_SNA  30720
#define S_SNB  30976
#define S_RV   31488
#define S_RI   32512

__device__ __forceinline__ void scores_body(char* smem, int sid,
                                            const float* __restrict__ x) {
    uint32_t sb = smem_u32(smem);
    __half* Ah = reinterpret_cast<__half*>(smem + S_AH);
    __half* Al = reinterpret_cast<__half*>(smem + S_AL);
    __half* Bh = reinterpret_cast<__half*>(smem + S_BH);
    __half* Bl = reinterpret_cast<__half*>(smem + S_BL);
    float*  snA = reinterpret_cast<float*>(smem + S_SNA);
    float*  snB = reinterpret_cast<float*>(smem + S_SNB);
    float*  rv  = reinterpret_cast<float*>(smem + S_RV);
    int*    ri  = reinterpret_cast<int*>(smem + S_RI);

    int bk = sid >> 1;
    int lo = (sid & 1) * 64;
    const float* ctx = x + (size_t)(bk * 2) * LL * DD + (size_t)lo * DD;
    const float* ent = x + (size_t)(bk * 2 + 1) * LL * DD;

    int t    = threadIdx.x;
    int lane = t & 31;
    int wid  = t >> 5;
    int wm   = wid & 1;
    int wn   = wid >> 1;
    int lq   = lane >> 2;
    int lr   = lane & 3;

    if (t < 64)  snA[t] = g_norm[(bk * 2) * LL + lo + t];
    if (t < 128) snB[t] = g_norm[(bk * 2 + 1) * LL + t];

    int arow[2], ak4[2];
    #pragma unroll
    for (int it = 0; it < 2; it++) {
        int idx = t + it * 256;
        arow[it] = idx >> 3;  ak4[it] = idx & 7;
    }
    int brow[4], bk4[4];
    #pragma unroll
    for (int it = 0; it < 4; it++) {
        int idx = t + it * 256;
        brow[it] = idx >> 3;  bk4[it] = idx & 7;
    }

    uint32_t frag_a = (uint32_t)(((wm * 32 + (lane & 15)) * ASTRH + (lane >> 4) * 8) * 2);
    uint32_t b_row_off = ((lane >> 4) * 8 + (lane & 7));
    uint32_t b_k_off   = ((lane >> 3) & 1) * 8;
    uint32_t frag_b = (uint32_t)(((wn * 32 + b_row_off) * ASTRH + b_k_off) * 2);

    uint32_t ah_base = sb + S_AH + frag_a;
    uint32_t al_base = sb + S_AL + frag_a;
    uint32_t bh_base = sb + S_BH + frag_b;
    uint32_t bl_base = sb + S_BL + frag_b;

    float acc[2][4][4];
    #pragma unroll
    for (int mi = 0; mi < 2; mi++)
        #pragma unroll
        for (int ni = 0; ni < 4; ni++)
            #pragma unroll
            for (int c = 0; c < 4; c++) acc[mi][ni][c] = 0.f;

    float4 av[2], bw[4];
    #pragma unroll
    for (int it = 0; it < 2; it++)
        av[it] = *reinterpret_cast<const float4*>(ctx + (size_t)arow[it] * DD + ak4[it] * 4);
    #pragma unroll
    for (int it = 0; it < 4; it++)
        bw[it] = *reinterpret_cast<const float4*>(ent + (size_t)brow[it] * DD + bk4[it] * 4);

    for (int c = 0; c < 24; c++) {
        #pragma unroll
        for (int it = 0; it < 2; it++) {
            uint32_t off = arow[it] * ASTRH + ak4[it] * 4;
            uint2 h, l;
            split2(av[it].x, av[it].y, h.x, l.x);
            split2(av[it].z, av[it].w, h.y, l.y);
            *reinterpret_cast<uint2*>(&Ah[off]) = h;
            *reinterpret_cast<uint2*>(&Al[off]) = l;
        }
        #pragma unroll
        for (int it = 0; it < 4; it++) {
            uint32_t off = brow[it] * ASTRH + bk4[it] * 4;
            uint2 h, l;
            split2(bw[it].x, bw[it].y, h.x, l.x);
            split2(bw[it].z, bw[it].w, h.y, l.y);
            *reinterpret_cast<uint2*>(&Bh[off]) = h;
            *reinterpret_cast<uint2*>(&Bl[off]) = l;
        }
        __syncthreads();
        if (c < 23) {
            int d0 = (c + 1) * 32;
            #pragma unroll
            for (int it = 0; it < 2; it++)
                av[it] = *reinterpret_cast<const float4*>(ctx + (size_t)arow[it] * DD + d0 + ak4[it] * 4);
            #pragma unroll
            for (int it = 0; it < 4; it++)
                bw[it] = *reinterpret_cast<const float4*>(ent + (size_t)brow[it] * DD + d0 + bk4[it] * 4);
        }
        #pragma unroll
        for (int kk = 0; kk < 2; kk++) {
            uint32_t ah[2][4], al[2][4];
            #pragma unroll
            for (int mi = 0; mi < 2; mi++) {
                ldsm_x4(ah[mi], ah_base + mi * (16 * ASTRH * 2) + kk * 32);
                ldsm_x4(al[mi], al_base + mi * (16 * ASTRH * 2) + kk * 32);
            }
            #pragma unroll
            for (int nb = 0; nb < 2; nb++) {
                uint32_t bh[4];
                ldsm_x4(bh, bh_base + nb * (16 * ASTRH * 2) + kk * 32);
                #pragma unroll
                for (int mi = 0; mi < 2; mi++) {
                    mma_fp16(acc[mi][nb * 2 + 0], ah[mi], &bh[0]);
                    mma_fp16(acc[mi][nb * 2 + 1], ah[mi], &bh[2]);
                    mma_fp16(acc[mi][nb * 2 + 0], al[mi], &bh[0]);
                    mma_fp16(acc[mi][nb * 2 + 1], al[mi], &bh[2]);
                }
                uint32_t bl[4];
                ldsm_x4(bl, bl_base + nb * (16 * ASTRH * 2) + kk * 32);
                #pragma unroll
                for (int mi = 0; mi < 2; mi++) {
                    mma_fp16(acc[mi][nb * 2 + 0], ah[mi], &bl[0]);
                    mma_fp16(acc[mi][nb * 2 + 1], ah[mi], &bl[2]);
                }
            }
        }
        __syncthreads();
    }

    float bv[4];
    int   bi4[4];
    float nl[4];
    #pragma unroll
    for (int s = 0; s < 4; s++) {
        bv[s] = -3.4e38f; bi4[s] = 0;
        nl[s] = snA[wm * 32 + (s >> 1) * 16 + (s & 1) * 8 + lq];
    }
    #pragma unroll
    for (int ni = 0; ni < 4; ni++) {
        int col0 = wn * 32 + ni * 8 + lr * 2;
        float nm0 = snB[col0], nm1 = snB[col0 + 1];
        #pragma unroll
        for (int mi = 0; mi < 2; mi++) {
            float c0 = acc[mi][ni][0] / (nl[mi * 2] * nm0 + EPSV);
            if (c0 > bv[mi * 2]) { bv[mi * 2] = c0; bi4[mi * 2] = col0; }
            float c1 = acc[mi][ni][1] / (nl[mi * 2] * nm1 + EPSV);
            if (c1 > bv[mi * 2]) { bv[mi * 2] = c1; bi4[mi * 2] = col0 + 1; }
            float c2 = acc[mi][ni][2] / (nl[mi * 2 + 1] * nm0 + EPSV);
            if (c2 > bv[mi * 2 + 1]) { bv[mi * 2 + 1] = c2; bi4[mi * 2 + 1] = col0; }
            float c3 = acc[mi][ni][3] / (nl[mi * 2 + 1] * nm1 + EPSV);
            if (c3 > bv[mi * 2 + 1]) { bv[mi * 2 + 1] = c3; bi4[mi * 2 + 1] = col0 + 1; }
        }
    }
    #pragma unroll
    for (int s = 0; s < 4; s++) {
        #pragma unroll
        for (int o = 1; o <= 2; o <<= 1) {
            float ov = __shfl_xor_sync(0xffffffffu, bv[s], o);
            int   oi = __shfl_xor_sync(0xffffffffu, bi4[s], o);
            if (ov > bv[s] || (ov == bv[s] && oi < bi4[s])) { bv[s] = ov; bi4[s] = oi; }
        }
    }
    if (lr == 0) {
        #pragma unroll
        for (int s = 0; s < 4; s++) {
            int row = wm * 32 + (s >> 1) * 16 + (s & 1) * 8 + lq;
            rv[row * 4 + wn] = bv[s];
            ri[row * 4 + wn] = bi4[s];
        }
    }
    __syncthreads();
    if (t < 64) {
        float best = rv[t * 4]; int bi = ri[t * 4];
        #pragma unroll
        for (int j = 1; j < 4; j++) {
            float v = rv[t * 4 + j];
            int   i = ri[t * 4 + j];
            if (v > best || (v == best && i < bi)) { best = v; bi = i; }
        }
        g_arg[bk * LL + lo + t] = bi;
    }
}

// ---------------------------------------------------------------------------
// Megakernel: parity-interleaved tensor+tensor bodies (R9-pattern merge of
// the R13-validated bodies). Even blocks = MLP tile, odd = scores half-tile.
// ---------------------------------------------------------------------------
__global__ __launch_bounds__(256, 2) void mega_kernel(const float* __restrict__ x,
                                                      const float* __restrict__ b1,
                                                      const float* __restrict__ w2,
                                                      const float* __restrict__ b2) {
    extern __shared__ char smem[];
    int id = blockIdx.x >> 1;
    if ((blockIdx.x & 1) == 0) {
        mlp_body(smem, id, b1, w2, b2);
    } else {
        scores_body(smem, id, x);
    }
}

// ---------------------------------------------------------------------------
// Kernel C: out = y_ctx + y_ent[argmax]
// ---------------------------------------------------------------------------
__global__ void finalize_kernel(float* __restrict__ out) {
    int i  = blockIdx.x * 256 + threadIdx.x;
    int bk = i >> 7;
    float yc = g_y[(bk * 2) * LL + (i & 127)];
    float ye = g_y[(bk * 2 + 1) * LL + g_arg[i]];
    out[i] = yc + ye;
}

extern "C" void kernel_launch(void* const* d_in, const int* in_sizes, int n_in,
                              void* d_out, int out_size) {
    const float* context = (const float*)d_in[0];
    const float* w1      = (const float*)d_in[1];
    const float* b1      = (const float*)d_in[2];
    const float* w2      = (const float*)d_in[3];
    const float* b2      = (const float*)d_in[4];
    float* out = (float*)d_out;

    cudaFuncSetAttribute(mega_kernel,
                         cudaFuncAttributeMaxDynamicSharedMemorySize, MEGA_SMEM);

    prep_w1_kernel<<<DD, 256>>>(w1);
    prep_x_kernel<<<NROWS / 8, 256>>>(context);
    mega_kernel<<<1024, 256, MEGA_SMEM>>>(context, b1, w2, b2);
    finalize_kernel<<<NOUT / 256, 256>>>(out);
}